// round 14
// baseline (speedup 1.0000x reference)
#include <cuda_runtime.h>
#include <math.h>

#define BB 64
#define TT 2048
#define HH 512
#define QQ 512
#define NCHUNK 16
#define CHUNK (TT / NCHUNK)   // 128 rows per chunk
#define QSPLIT 16
#define QSEG (QQ / QSPLIT)    // 32

// Scratch (allocation-free rule: __device__ globals)
__device__ __align__(16) float g_vp[QSPLIT * BB * HH];   // partial v (2 MB)
__device__ __align__(16) float g_v[BB * HH];             // final v (128 KB)
__device__ int   g_len[BB];                              // valid length per batch
__device__ int   g_cnt[BB];                              // arrival counters
__device__ float g_pm[BB * NCHUNK];                      // per-chunk running max
__device__ float g_ps[BB * NCHUNK];                      // per-chunk exp-sum
__device__ __align__(16) float g_pctx[BB * NCHUNK * HH]; // per-chunk weighted ctx (2 MB)

__device__ __forceinline__ void cpa16(void* smem, const void* gmem) {
    unsigned s = (unsigned)__cvta_generic_to_shared(smem);
    asm volatile("cp.async.cg.shared.global [%0], [%1], 16;" :: "r"(s), "l"(gmem));
}

// ---------------------------------------------------------------------------
// Kernel 1: K-split partial matvec (frozen: 6.6 us).
// grid (QSPLIT=16, 16) = 256 blocks, 256 threads (8 warps).
// ---------------------------------------------------------------------------
#define K1_BGRP   4
#define K1_ROWS   4
#define K1_NBUF   4
#define K1_STAGES (QSEG / K1_ROWS)   // 8

__global__ __launch_bounds__(256) void k1_proj(const float* __restrict__ query,
                                               const float* __restrict__ W) {
    const int qz = blockIdx.x;
    const int b0 = blockIdx.y * K1_BGRP;
    const int tid = threadIdx.x;
    const int h4 = tid & 127;
    const int bh = tid >> 7;              // 0: batches b0,b0+1  1: b0+2,b0+3

    __shared__ float sq[K1_BGRP][QSEG];                         // 0.5 KB
    __shared__ __align__(16) float4 sw[K1_NBUF][K1_ROWS * 128]; // 32 KB

    if (tid < K1_BGRP * QSEG)
        sq[tid >> 5][tid & 31] = query[(b0 + (tid >> 5)) * QQ + qz * QSEG + (tid & 31)];

    const float4* Wg = (const float4*)W + (size_t)qz * QSEG * (HH / 4);

#pragma unroll
    for (int s = 0; s < K1_NBUF - 1; s++) {
        cpa16(&sw[s][tid],       Wg + s * 512 + tid);
        cpa16(&sw[s][tid + 256], Wg + s * 512 + tid + 256);
        asm volatile("cp.async.commit_group;");
    }
    __syncthreads();                      // sq visible

    float4 a0 = make_float4(0.f, 0.f, 0.f, 0.f), a1 = a0;
    const int bq0 = 2 * bh, bq1 = 2 * bh + 1;

#pragma unroll
    for (int s = 0; s < K1_STAGES; s++) {
        asm volatile("cp.async.wait_group %0;" :: "n"(K1_NBUF - 2));
        __syncthreads();                  // staged stage-s data visible to all
        const int buf = s & (K1_NBUF - 1);
#pragma unroll
        for (int r = 0; r < K1_ROWS; r++) {
            const float4 w = sw[buf][r * 128 + h4];
            const int qi = s * K1_ROWS + r;
            const float q0 = sq[bq0][qi], q1 = sq[bq1][qi];
            a0.x = fmaf(w.x, q0, a0.x); a0.y = fmaf(w.y, q0, a0.y);
            a0.z = fmaf(w.z, q0, a0.z); a0.w = fmaf(w.w, q0, a0.w);
            a1.x = fmaf(w.x, q1, a1.x); a1.y = fmaf(w.y, q1, a1.y);
            a1.z = fmaf(w.z, q1, a1.z); a1.w = fmaf(w.w, q1, a1.w);
        }
        const int sn = s + K1_NBUF - 1;
        if (sn < K1_STAGES) {
            const int nb = sn & (K1_NBUF - 1);
            cpa16(&sw[nb][tid],       Wg + sn * 512 + tid);
            cpa16(&sw[nb][tid + 256], Wg + sn * 512 + tid + 256);
        }
        asm volatile("cp.async.commit_group;");
    }

    float4* vp = (float4*)g_vp + (size_t)qz * BB * (HH / 4);
    vp[(b0 + bq0) * (HH / 4) + h4] = a0;
    vp[(b0 + bq1) * (HH / 4) + h4] = a1;
}

// ---------------------------------------------------------------------------
// Kernel 1b: hoisted per-batch preamble. grid (BB=64), 128 threads.
// Also zeroes the arrival counter (graph-replay determinism).
// ---------------------------------------------------------------------------
__global__ __launch_bounds__(128) void k1b_reduce(const int* __restrict__ tgt_raw) {
    const int b = blockIdx.x;
    const int tid = threadIdx.x;          // h-float4 slot

    float4 a = make_float4(0.f, 0.f, 0.f, 0.f);
#pragma unroll
    for (int z = 0; z < QSPLIT; z++) {
        const float4 p = ((const float4*)g_vp)[((size_t)z * BB + b) * (HH / 4) + tid];
        a.x += p.x; a.y += p.y; a.z += p.z; a.w += p.w;
    }
    ((float4*)g_v)[b * (HH / 4) + tid] = a;

    if (tid == 0) {
        int odd_or = 0;
#pragma unroll
        for (int i = 1; i < 2 * BB; i += 2) odd_or |= tgt_raw[i];
        const int is64 = (odd_or == 0);
        g_len[b] = (is64 ? tgt_raw[2 * b] : tgt_raw[b]) + 1;
    }
    if (tid == 1) g_cnt[b] = 0;
}

// ---------------------------------------------------------------------------
// Kernel 2: flash pass + fused last-block combine.
// ---------------------------------------------------------------------------
#define K2_NSTAGE 3

__device__ __forceinline__ float dot4(float4 a, float4 b) {
    return a.x * b.x + a.y * b.y + a.z * b.z + a.w * b.w;
}

#define PROCESS_ROW(E0, E1, E2, E3)                                              \
    {                                                                            \
        float d = dot4(E0, va) + dot4(E1, vb) + dot4(E2, vc) + dot4(E3, vd);     \
        d += __shfl_xor_sync(0xFFFFFFFFu, d, 16);                                \
        d += __shfl_xor_sync(0xFFFFFFFFu, d, 8);                                 \
        d += __shfl_xor_sync(0xFFFFFFFFu, d, 4);                                 \
        d += __shfl_xor_sync(0xFFFFFFFFu, d, 2);                                 \
        d += __shfl_xor_sync(0xFFFFFFFFu, d, 1);                                 \
        if (d > m) {                                                             \
            const float alpha = __expf(m - d);                                   \
            m = d;                                                               \
            ssum = ssum * alpha + 1.f;                                           \
            c0.x = c0.x * alpha + E0.x; c0.y = c0.y * alpha + E0.y;              \
            c0.z = c0.z * alpha + E0.z; c0.w = c0.w * alpha + E0.w;              \
            c1.x = c1.x * alpha + E1.x; c1.y = c1.y * alpha + E1.y;              \
            c1.z = c1.z * alpha + E1.z; c1.w = c1.w * alpha + E1.w;              \
            c2.x = c2.x * alpha + E2.x; c2.y = c2.y * alpha + E2.y;              \
            c2.z = c2.z * alpha + E2.z; c2.w = c2.w * alpha + E2.w;              \
            c3.x = c3.x * alpha + E3.x; c3.y = c3.y * alpha + E3.y;              \
            c3.z = c3.z * alpha + E3.z; c3.w = c3.w * alpha + E3.w;              \
        } else {                                                                 \
            const float p = __expf(d - m);                                       \
            ssum += p;                                                           \
            c0.x = fmaf(p, E0.x, c0.x); c0.y = fmaf(p, E0.y, c0.y);              \
            c0.z = fmaf(p, E0.z, c0.z); c0.w = fmaf(p, E0.w, c0.w);              \
            c1.x = fmaf(p, E1.x, c1.x); c1.y = fmaf(p, E1.y, c1.y);              \
            c1.z = fmaf(p, E1.z, c1.z); c1.w = fmaf(p, E1.w, c1.w);              \
            c2.x = fmaf(p, E2.x, c2.x); c2.y = fmaf(p, E2.y, c2.y);              \
            c2.z = fmaf(p, E2.z, c2.z); c2.w = fmaf(p, E2.w, c2.w);              \
            c3.x = fmaf(p, E3.x, c3.x); c3.y = fmaf(p, E3.y, c3.y);              \
            c3.z = fmaf(p, E3.z, c3.z); c3.w = fmaf(p, E3.w, c3.w);              \
        }                                                                        \
    }

__global__ __launch_bounds__(256, 4) void k2_flash(const float* __restrict__ enc,
                                                   float* __restrict__ out) {
    __shared__ __align__(16) float4 sbuf[K2_NSTAGE][8 * 128];   // 48 KB (static max)
    __shared__ int s_last;

    const int b = blockIdx.y;
    const int c = blockIdx.x;
    const int tid = threadIdx.x, w = tid >> 5, lane = tid & 31;

    const int L = g_len[b];                      // valid rows: t in [0, L)
    const int t0 = c * CHUNK;

    if (t0 < L) {                                // ---- active chunk: flash body ----
        const int tend = min(t0 + CHUNK, L);
        const int total = (tend - t0 + 7) >> 3;  // stages for this block

        const float4* v4 = (const float4*)g_v + b * (HH / 4);
        const float4 va = v4[lane], vb = v4[lane + 32], vc = v4[lane + 64], vd = v4[lane + 96];

        const float4* ebase = (const float4*)enc + (size_t)b * TT * (HH / 4);

#pragma unroll
        for (int st = 0; st < K2_NSTAGE; st++) {
            const int row = t0 + st * 8 + w;
            if (row < tend) {
                const float4* src = ebase + (size_t)row * 128;
#pragma unroll
                for (int k = 0; k < 4; k++)
                    cpa16(&sbuf[st][w * 128 + lane + k * 32], src + lane + k * 32);
            }
            asm volatile("cp.async.commit_group;");
        }

        float m = -INFINITY, ssum = 0.f;
        float4 c0 = make_float4(0.f, 0.f, 0.f, 0.f), c1 = c0, c2 = c0, c3 = c0;

        for (int st = 0; st < total; st++) {
            asm volatile("cp.async.wait_group %0;" :: "n"(K2_NSTAGE - 1));
            const int buf = st % K2_NSTAGE;
            const int row = t0 + st * 8 + w;
            if (row < tend) {
                const float4 e0 = sbuf[buf][w * 128 + lane];
                const float4 e1 = sbuf[buf][w * 128 + lane + 32];
                const float4 e2 = sbuf[buf][w * 128 + lane + 64];
                const float4 e3 = sbuf[buf][w * 128 + lane + 96];
                PROCESS_ROW(e0, e1, e2, e3);
            }
            const int row2 = t0 + (st + K2_NSTAGE) * 8 + w;
            if (row2 < tend) {
                const float4* src = ebase + (size_t)row2 * 128;
#pragma unroll
                for (int k = 0; k < 4; k++)
                    cpa16(&sbuf[buf][w * 128 + lane + k * 32], src + lane + k * 32);
            }
            asm volatile("cp.async.commit_group;");
        }
        asm volatile("cp.async.wait_group 0;");
        __syncthreads();                          // pipeline drained; reuse sbuf

        // ---- combine 8 warps: overlay sctx/sM/sS on sbuf ----
        float* sctx = (float*)sbuf;               // [8][512] = 16 KB
        float* sMv  = (float*)sbuf + 8 * HH;
        float* sSv  = sMv + 8;

        float4* sc4 = (float4*)(sctx + w * HH);
        sc4[lane] = c0; sc4[lane + 32] = c1; sc4[lane + 64] = c2; sc4[lane + 96] = c3;
        if (lane == 0) { sMv[w] = m; sSv[w] = ssum; }
        __syncthreads();

        float M = -INFINITY;
#pragma unroll
        for (int i = 0; i < 8; i++) if (sSv[i] > 0.f) M = fmaxf(M, sMv[i]);
        float S = 0.f, f[8];
#pragma unroll
        for (int i = 0; i < 8; i++) {
            f[i] = (sSv[i] > 0.f) ? __expf(sMv[i] - M) : 0.f;
            S += sSv[i] * f[i];
        }
        const int base = (b * NCHUNK + c) * HH;
        for (int h = tid; h < HH; h += 256) {
            float a = 0.f;
#pragma unroll
            for (int i = 0; i < 8; i++) a = fmaf(sctx[i * HH + h], f[i], a);
            g_pctx[base + h] = a;
        }
        if (tid == 0) { g_pm[b * NCHUNK + c] = M; g_ps[b * NCHUNK + c] = S; }
    } else {                                      // ---- masked chunk ----
        if (tid == 0) g_ps[b * NCHUNK + c] = 0.f;
    }

    // ---- arrival protocol: last block for batch b does the final combine ----
    __threadfence();                              // each thread's writes visible
    __syncthreads();                              // all fences done
    if (tid == 0) s_last = (atomicAdd(&g_cnt[b], 1) == NCHUNK - 1);
    __syncthreads();
    if (!s_last) return;
    __threadfence();                              // order: counter read -> data reads

    // final combine for batch b (pm/ps/pctx are L2-hot — just written)
    float* spm2 = (float*)sbuf;                   // reuse smem (all threads past use)
    float* sps2 = spm2 + NCHUNK;
    float* sfct = sps2 + NCHUNK;
    __syncthreads();                              // everyone past prior smem reads
    if (tid < NCHUNK)              spm2[tid] = g_pm[b * NCHUNK + tid];
    else if (tid < 2 * NCHUNK)     sps2[tid - NCHUNK] = g_ps[b * NCHUNK + tid - NCHUNK];
    __syncthreads();

    float M2 = -INFINITY;
#pragma unroll
    for (int cc = 0; cc < NCHUNK; cc++)
        if (sps2[cc] > 0.f) M2 = fmaxf(M2, spm2[cc]);
    if (tid < NCHUNK)
        sfct[tid] = (sps2[tid] > 0.f) ? __expf(spm2[tid] - M2) : 0.f;
    __syncthreads();

    float S2 = 0.f;
#pragma unroll
    for (int cc = 0; cc < NCHUNK; cc++) S2 += sps2[cc] * sfct[cc];

    const float inv = 1.f / S2;
    for (int h = tid; h < HH; h += 256) {
        float acc = 0.f;
#pragma unroll
        for (int cc = 0; cc < NCHUNK; cc++)
            acc = fmaf(g_pctx[(b * NCHUNK + cc) * HH + h], sfct[cc], acc);
        out[b * HH + h] = acc * inv;
    }
}

// ---------------------------------------------------------------------------
extern "C" void kernel_launch(void* const* d_in, const int* in_sizes, int n_in,
                              void* d_out, int out_size) {
    const float* query = nullptr;
    const float* enc   = nullptr;
    const float* W     = nullptr;
    const int*   tgt   = nullptr;   // dtype (i32 vs i64) detected on device
    for (int i = 0; i < n_in; i++) {
        switch (in_sizes[i]) {
            case BB * QQ:               query = (const float*)d_in[i]; break;
            case BB * TT * HH:          enc   = (const float*)d_in[i]; break;
            case QQ * HH:               W     = (const float*)d_in[i]; break;
            case BB:                    tgt   = (const int*)d_in[i]; break;
            default: break;             // bias (512) unused: softmax-shift invariant
        }
    }

    k1_proj<<<dim3(QSPLIT, BB / K1_BGRP), 256>>>(query, W);
    k1b_reduce<<<BB, 128>>>(tgt);
    k2_flash<<<dim3(NCHUNK, BB), 256>>>(enc, (float*)d_out);
}